// round 10
// baseline (speedup 1.0000x reference)
#include <cuda_runtime.h>
#include <cuda_fp16.h>
#include <cstdint>

#define NN   55296      // 6*96*96 nodes
#define NE   221184     // edges
#define H    32
#define HH   1024       // H*H
#define BB   2          // batch

// -------- device scratch (static: allocation-free kernel_launch) --------
__device__ __half g_We[(size_t)NE * HH];          // 453 MB  [E][h*32+o] fp16
__device__ unsigned g_Bfrag[512 * 32 * 2];        // 128 KB fragment-ordered tf32 ew2
__device__ float g_node[(size_t)BB * NN * H];
__device__ float g_hidden[(size_t)BB * NN * H];
__device__ float g_agg[(size_t)BB * NN * H];

#define FULL 0xffffffffu

__device__ __forceinline__ unsigned f2tf32(float f) {
    unsigned r; asm("cvt.rna.tf32.f32 %0, %1;" : "=r"(r) : "f"(f)); return r;
}

// fast activations (MUFU-based, ~1e-6 err, overflow-safe)
__device__ __forceinline__ float fsigmoid(float x) {
    return __fdividef(1.f, 1.f + __expf(-x));
}
__device__ __forceinline__ float ftanh(float x) {
    return 1.f - __fdividef(2.f, __expf(2.f * x) + 1.f);
}

// ---------------------------------------------------------------
// h0 = relu(x@pw1 + pb1)@pw2 + pb2   (warp per (b,node), lane = channel)
// Also zero-inits g_agg for step 0.
// ---------------------------------------------------------------
__global__ __launch_bounds__(256) void k_h0(
    const float* __restrict__ x,
    const float* __restrict__ pw1, const float* __restrict__ pb1,
    const float* __restrict__ pw2, const float* __restrict__ pb2)
{
    int warp = (blockIdx.x * blockDim.x + threadIdx.x) >> 5;
    int lane = threadIdx.x & 31;
    if (warp >= BB * NN) return;
    size_t base = (size_t)warp * H;

    float v = x[base + lane];
    float acc = pb1[lane];
#pragma unroll
    for (int c = 0; c < H; c++)
        acc = fmaf(__shfl_sync(FULL, v, c), pw1[c * H + lane], acc);
    float hid = fmaxf(acc, 0.f);

    float acc2 = pb2[lane];
#pragma unroll
    for (int k = 0; k < H; k++)
        acc2 = fmaf(__shfl_sync(FULL, hid, k), pw2[k * H + lane], acc2);

    g_node[base + lane]   = acc2;
    g_hidden[base + lane] = acc2;
    g_agg[base + lane]    = 0.f;
}

// ---------------------------------------------------------------
// k_prep: shuffle ew2 [32][1024] fp32 into fragment-ordered tf32 for
// mma.sync.m16n8k8 B operands (col-major k8 x n8 tiles).
// Fragment (nt, ks): lane holds (b0, b1):
//   b0 = ew2[ks*8 + lane%4    ][nt*8 + lane/4]
//   b1 = ew2[ks*8 + lane%4 + 4][nt*8 + lane/4]
// Stored at g_Bfrag[((nt*32 + lane)*4 + ks)*2 + {0,1}]  -> per-lane 32B run.
// ---------------------------------------------------------------
__global__ __launch_bounds__(256) void k_prep(const float* __restrict__ ew2)
{
    int idx = blockIdx.x * blockDim.x + threadIdx.x;   // 0 .. 16383
    if (idx >= 128 * 32 * 4) return;
    int ks   = idx & 3;
    int lane = (idx >> 2) & 31;
    int nt   = idx >> 7;
    int tg = lane & 3, g = lane >> 2;
    int col = nt * 8 + g;
    float v0 = ew2[(ks * 8 + tg)     * HH + col];
    float v1 = ew2[(ks * 8 + tg + 4) * HH + col];
    g_Bfrag[2 * idx]     = f2tf32(v0);
    g_Bfrag[2 * idx + 1] = f2tf32(v1);
}

// ---------------------------------------------------------------
// k_We_mma: We[e] = relu(rel[e]@ew1 + eb1) @ ew2 + eb2 -> fp16
// Block = 128 threads (4 warps) = 64 edges; warp = 16 edges (m16).
// tf32 m16n8k8 mma, 4 k-steps, 128 n-tiles.
// ---------------------------------------------------------------
__global__ __launch_bounds__(128) void k_We_mma(
    const float* __restrict__ rel,
    const float* __restrict__ ew1, const float* __restrict__ eb1,
    const float* __restrict__ eb2)
{
    __shared__ unsigned smA[64][33];   // tf32 hid, padded vs bank conflicts
    __shared__ float smBias[1024];

    int tid  = threadIdx.x;
    int eBase = blockIdx.x * 64;

    // ---- compute hid (A operand) for 64 edges ----
    {
        int c = tid & 31;                 // channel (fixed per thread)
        float b  = eb1[c];
        float w0 = ew1[0 * H + c], w1 = ew1[1 * H + c],
              w2 = ew1[2 * H + c], w3 = ew1[3 * H + c];
#pragma unroll
        for (int j = 0; j < 16; j++) {
            int e_loc = (tid >> 5) + j * 4;
            const float* r = rel + (size_t)(eBase + e_loc) * 4;
            float a = b;
            a = fmaf(r[0], w0, a); a = fmaf(r[1], w1, a);
            a = fmaf(r[2], w2, a); a = fmaf(r[3], w3, a);
            smA[e_loc][c] = f2tf32(fmaxf(a, 0.f));
        }
    }
    // ---- stage bias ----
    for (int i = tid; i < 1024; i += 128) smBias[i] = eb2[i];
    __syncthreads();

    int warp = tid >> 5;
    int lane = tid & 31;
    int tg = lane & 3, g = lane >> 2;
    int wrow = warp * 16;

    // ---- A fragments: 4 ksteps x 4 regs, reused across all n-tiles ----
    unsigned a[4][4];
#pragma unroll
    for (int ks = 0; ks < 4; ks++) {
        a[ks][0] = smA[wrow + g    ][ks * 8 + tg];
        a[ks][1] = smA[wrow + g + 8][ks * 8 + tg];
        a[ks][2] = smA[wrow + g    ][ks * 8 + tg + 4];
        a[ks][3] = smA[wrow + g + 8][ks * 8 + tg + 4];
    }

    const uint4* bf = (const uint4*)g_Bfrag;
    size_t row0 = (size_t)(eBase + wrow + g) * HH;
    size_t row1 = row0 + 8 * HH;

#pragma unroll 2
    for (int nt = 0; nt < 128; nt++) {
        int col = nt * 8 + 2 * tg;
        float bias0 = smBias[col], bias1 = smBias[col + 1];
        float c0 = bias0, c1 = bias1, c2 = bias0, c3 = bias1;

        uint4 q0 = bf[(nt * 32 + lane) * 2];       // ks0: (x,y)  ks1: (z,w)
        uint4 q1 = bf[(nt * 32 + lane) * 2 + 1];   // ks2: (x,y)  ks3: (z,w)

#define MMA(ks, b0v, b1v) \
        asm volatile("mma.sync.aligned.m16n8k8.row.col.f32.tf32.tf32.f32 " \
            "{%0,%1,%2,%3}, {%4,%5,%6,%7}, {%8,%9}, {%0,%1,%2,%3};" \
            : "+f"(c0), "+f"(c1), "+f"(c2), "+f"(c3) \
            : "r"(a[ks][0]), "r"(a[ks][1]), "r"(a[ks][2]), "r"(a[ks][3]), \
              "r"(b0v), "r"(b1v));
        MMA(0, q0.x, q0.y)
        MMA(1, q0.z, q0.w)
        MMA(2, q1.x, q1.y)
        MMA(3, q1.z, q1.w)
#undef MMA

        __half2 h01 = __floats2half2_rn(c0, c1);
        __half2 h23 = __floats2half2_rn(c2, c3);
        *(unsigned*)(&g_We[row0 + col]) = *reinterpret_cast<unsigned*>(&h01);
        *(unsigned*)(&g_We[row1 + col]) = *reinterpret_cast<unsigned*>(&h23);
    }
}

// ---------------------------------------------------------------
// message + scatter:  agg[b,dst] += node[b,src] @ We[e]   (warp per edge)
// ---------------------------------------------------------------
__global__ __launch_bounds__(256) void k_msg(
    const int* __restrict__ esrc, const int* __restrict__ edst)
{
    int e    = (blockIdx.x * blockDim.x + threadIdx.x) >> 5;
    int lane = threadIdx.x & 31;
    if (e >= NE) return;

    int s = esrc[e];
    int d = edst[e];
    int hi = lane >> 4;
    int q  = lane & 15;

    float n0 = g_node[(size_t)s * H + lane];
    float n1 = g_node[(size_t)(NN + s) * H + lane];

    const __half2* w = (const __half2*)(g_We + (size_t)e * HH);
    float2 a0 = {0.f, 0.f}, a1 = {0.f, 0.f};
#pragma unroll
    for (int hb = 0; hb < H; hb += 2) {
        __half2 v = __ldcs(w + hb * 16 + lane);   // streaming, 128B/warp
        float2 wf = __half22float2(v);
        int hrow = hb + hi;
        float s0 = __shfl_sync(FULL, n0, hrow);
        float s1 = __shfl_sync(FULL, n1, hrow);
        a0.x = fmaf(s0, wf.x, a0.x); a0.y = fmaf(s0, wf.y, a0.y);
        a1.x = fmaf(s1, wf.x, a1.x); a1.y = fmaf(s1, wf.y, a1.y);
    }
    a0.x += __shfl_xor_sync(FULL, a0.x, 16);
    a0.y += __shfl_xor_sync(FULL, a0.y, 16);
    a1.x += __shfl_xor_sync(FULL, a1.x, 16);
    a1.y += __shfl_xor_sync(FULL, a1.y, 16);

    if (hi == 0) {
        float* p0 = g_agg + (size_t)d * H + 2 * q;
        float* p1 = g_agg + (size_t)(NN + d) * H + 2 * q;
        atomicAdd(p0,     a0.x);
        atomicAdd(p0 + 1, a0.y);
        atomicAdd(p1,     a1.x);
        atomicAdd(p1 + 1, a1.y);
    }
}

// ---------------------------------------------------------------
// node = relu(agg + conv_b); GRU update. Thread per (b,node).
// Re-zeros g_agg for the next step (replaces k_zero).
// ---------------------------------------------------------------
__global__ __launch_bounds__(256) void k_gru(
    const float* __restrict__ conv_b,
    const float* __restrict__ wih, const float* __restrict__ whh,
    const float* __restrict__ bih, const float* __restrict__ bhh,
    float* __restrict__ out, int write_out)
{
    int n = blockIdx.x * blockDim.x + threadIdx.x;
    if (n >= BB * NN) return;
    size_t base = (size_t)n * H;

    float nd[H], hd[H];
    {
        float4* av = (float4*)(g_agg + base);
        const float4* hv = (const float4*)(g_hidden + base);
        const float4* cv = (const float4*)conv_b;
        float4 z4 = {0.f, 0.f, 0.f, 0.f};
#pragma unroll
        for (int qq = 0; qq < 8; qq++) {
            float4 a = av[qq], c = cv[qq], h4 = hv[qq];
            av[qq] = z4;                       // re-zero agg for next step
            nd[4*qq+0] = fmaxf(a.x + c.x, 0.f);
            nd[4*qq+1] = fmaxf(a.y + c.y, 0.f);
            nd[4*qq+2] = fmaxf(a.z + c.z, 0.f);
            nd[4*qq+3] = fmaxf(a.w + c.w, 0.f);
            hd[4*qq+0] = h4.x; hd[4*qq+1] = h4.y; hd[4*qq+2] = h4.z; hd[4*qq+3] = h4.w;
        }
    }

    const float4* wi = (const float4*)wih;   // rows of 8 float4
    const float4* wh = (const float4*)whh;

#pragma unroll 1
    for (int o = 0; o < H; o++) {
        float xr = 0.f, xz = 0.f, xn = 0.f, hr = 0.f, hz = 0.f, hn = 0.f;
#pragma unroll
        for (int qq = 0; qq < 8; qq++) {
            float4 w;
#define DOT(accv, srcarr, row) { w = (row)[qq]; \
            accv = fmaf(srcarr[4*qq+0], w.x, accv); accv = fmaf(srcarr[4*qq+1], w.y, accv); \
            accv = fmaf(srcarr[4*qq+2], w.z, accv); accv = fmaf(srcarr[4*qq+3], w.w, accv); }
            DOT(xr, nd, wi + (size_t)(o)      * 8)
            DOT(xz, nd, wi + (size_t)(o + 32) * 8)
            DOT(xn, nd, wi + (size_t)(o + 64) * 8)
            DOT(hr, hd, wh + (size_t)(o)      * 8)
            DOT(hz, hd, wh + (size_t)(o + 32) * 8)
            DOT(hn, hd, wh + (size_t)(o + 64) * 8)
#undef DOT
        }
        float rg = fsigmoid(xr + hr + bih[o]      + bhh[o]);
        float zg = fsigmoid(xz + hz + bih[o + 32] + bhh[o + 32]);
        float ng = ftanh(xn + bih[o + 64] + rg * (hn + bhh[o + 64]));
        float hprev = hd[o];
        float newh = (1.f - zg) * ng + zg * hprev;
        g_hidden[base + o] = newh;
        g_node[base + o]   = newh;
        if (write_out) out[base + o] = newh;
    }
}

// ---------------------------------------------------------------
extern "C" void kernel_launch(void* const* d_in, const int* in_sizes, int n_in,
                              void* d_out, int out_size)
{
    const float* x      = (const float*)d_in[0];
    const float* rel    = (const float*)d_in[1];
    const float* pw1    = (const float*)d_in[2];
    const float* pb1    = (const float*)d_in[3];
    const float* pw2    = (const float*)d_in[4];
    const float* pb2    = (const float*)d_in[5];
    const float* ew1    = (const float*)d_in[6];
    const float* eb1    = (const float*)d_in[7];
    const float* ew2    = (const float*)d_in[8];
    const float* eb2    = (const float*)d_in[9];
    const float* conv_b = (const float*)d_in[10];
    const float* wih    = (const float*)d_in[11];
    const float* whh    = (const float*)d_in[12];
    const float* bih    = (const float*)d_in[13];
    const float* bhh    = (const float*)d_in[14];
    const int*   esrc   = (const int*)d_in[15];
    const int*   edst   = (const int*)d_in[16];
    float* out = (float*)d_out;

    k_h0<<<13824, 256>>>(x, pw1, pb1, pw2, pb2);
    k_prep<<<64, 256>>>(ew2);
    k_We_mma<<<3456, 128>>>(rel, ew1, eb1, eb2);   // 64 edges / block

    for (int s = 0; s < 3; s++) {
        k_msg<<<27648, 256>>>(esrc, edst);
        k_gru<<<432, 256>>>(conv_b, wih, whh, bih, bhh, out, (s == 2) ? 1 : 0);
    }
}

// round 14
// speedup vs baseline: 1.2021x; 1.2021x over previous
#include <cuda_runtime.h>
#include <cuda_fp16.h>
#include <cstdint>

#define NN   55296      // 6*96*96 nodes
#define NE   221184     // edges
#define H    32
#define HH   1024       // H*H
#define BB   2          // batch

// -------- device scratch (static: allocation-free kernel_launch) --------
__device__ __half g_We[(size_t)NE * HH];          // 453 MB  [E][h*32+o] fp16
__device__ unsigned g_Bfrag[128 * 32 * 4];        // 64 KB fp16 fragment-packed ew2
__device__ float g_node[(size_t)BB * NN * H];
__device__ float g_hidden[(size_t)BB * NN * H];
__device__ float g_agg[(size_t)BB * NN * H];

#define FULL 0xffffffffu

// fast activations (MUFU-based, ~1e-6 err, overflow-safe)
__device__ __forceinline__ float fsigmoid(float x) {
    return __fdividef(1.f, 1.f + __expf(-x));
}
__device__ __forceinline__ float ftanh(float x) {
    return 1.f - __fdividef(2.f, __expf(2.f * x) + 1.f);
}
__device__ __forceinline__ unsigned smem_u32(const void* p) {
    return (unsigned)__cvta_generic_to_shared(p);
}

// ---------------------------------------------------------------
// h0 = relu(x@pw1 + pb1)@pw2 + pb2   (warp per (b,node), lane = channel)
// Also zero-inits g_agg for step 0.
// ---------------------------------------------------------------
__global__ __launch_bounds__(256) void k_h0(
    const float* __restrict__ x,
    const float* __restrict__ pw1, const float* __restrict__ pb1,
    const float* __restrict__ pw2, const float* __restrict__ pb2)
{
    int warp = (blockIdx.x * blockDim.x + threadIdx.x) >> 5;
    int lane = threadIdx.x & 31;
    if (warp >= BB * NN) return;
    size_t base = (size_t)warp * H;

    float v = x[base + lane];
    float acc = pb1[lane];
#pragma unroll
    for (int c = 0; c < H; c++)
        acc = fmaf(__shfl_sync(FULL, v, c), pw1[c * H + lane], acc);
    float hid = fmaxf(acc, 0.f);

    float acc2 = pb2[lane];
#pragma unroll
    for (int k = 0; k < H; k++)
        acc2 = fmaf(__shfl_sync(FULL, hid, k), pw2[k * H + lane], acc2);

    g_node[base + lane]   = acc2;
    g_hidden[base + lane] = acc2;
    g_agg[base + lane]    = 0.f;
}

// ---------------------------------------------------------------
// k_prep: pack ew2 [32][1024] fp32 -> fp16 B fragments for
// mma.sync.m16n8k16.row.col (B col-major: k16 x n8 per tile).
// Lane (g=lane>>2, tg=lane&3), tile nt, kstep ks (kbase=16*ks):
//   b0 = (ew2[kb+2tg  ][nt*8+g], ew2[kb+2tg+1][nt*8+g])
//   b1 = (ew2[kb+2tg+8][nt*8+g], ew2[kb+2tg+9][nt*8+g])
// g_Bfrag[(nt*32+lane)*4 + ks*2 + {0,1}] -> one uint4 per (nt,lane).
// ---------------------------------------------------------------
__global__ __launch_bounds__(256) void k_prep(const float* __restrict__ ew2)
{
    int idx = blockIdx.x * blockDim.x + threadIdx.x;   // 0 .. 8191
    if (idx >= 128 * 32 * 2) return;
    int ks   = idx & 1;
    int lane = (idx >> 1) & 31;
    int nt   = idx >> 6;
    int tg = lane & 3, g = lane >> 2;
    int col = nt * 8 + g;
    int kb  = ks * 16;
    __half2 b0 = __floats2half2_rn(ew2[(kb + 2*tg    ) * HH + col],
                                   ew2[(kb + 2*tg + 1) * HH + col]);
    __half2 b1 = __floats2half2_rn(ew2[(kb + 2*tg + 8) * HH + col],
                                   ew2[(kb + 2*tg + 9) * HH + col]);
    unsigned* dst = g_Bfrag + (nt * 32 + lane) * 4 + ks * 2;
    dst[0] = *reinterpret_cast<unsigned*>(&b0);
    dst[1] = *reinterpret_cast<unsigned*>(&b1);
}

// ---------------------------------------------------------------
// k_We_mma v2: We[e] = relu(rel[e]@ew1 + eb1) @ ew2 + eb2 -> fp16
// Block = 128 threads (4 warps) = 64 edges; warp = 16 edges (m16).
// fp16 m16n8k16 mma (2 k-steps), 128 n-tiles in 16 chunks of 8.
// Results staged per-chunk in smem via stmatrix, then coalesced
// 128B-row STG.128 to gmem (kills the scattered-store wavefronts).
// ---------------------------------------------------------------
__global__ __launch_bounds__(128) void k_We_mma(
    const float* __restrict__ rel,
    const float* __restrict__ ew1, const float* __restrict__ eb1,
    const float* __restrict__ eb2)
{
    __shared__ float    smAf[64][33];      // fp32 hid
    __shared__ unsigned smA2[64][17];      // half2-packed hid
    __shared__ float    smBias[1024];
    __shared__ __align__(16) char smC[64 * 144];  // chunk: 64 rows x 128B (+16B pad)

    int tid   = threadIdx.x;
    int eBase = blockIdx.x * 64;

    // ---- compute hid (A operand) for 64 edges ----
    {
        int c = tid & 31;
        float b  = eb1[c];
        float w0 = ew1[0 * H + c], w1 = ew1[1 * H + c],
              w2 = ew1[2 * H + c], w3 = ew1[3 * H + c];
#pragma unroll
        for (int j = 0; j < 16; j++) {
            int e_loc = (tid >> 5) + j * 4;
            const float* r = rel + (size_t)(eBase + e_loc) * 4;
            float a = b;
            a = fmaf(r[0], w0, a); a = fmaf(r[1], w1, a);
            a = fmaf(r[2], w2, a); a = fmaf(r[3], w3, a);
            smAf[e_loc][c] = fmaxf(a, 0.f);
        }
    }
    for (int i = tid; i < 1024; i += 128) smBias[i] = eb2[i];
    __syncthreads();

    // pack hid to half2
    for (int i = tid; i < 64 * 16; i += 128) {
        int e = i >> 4, c2 = i & 15;
        __half2 hv = __floats2half2_rn(smAf[e][2 * c2], smAf[e][2 * c2 + 1]);
        smA2[e][c2] = *reinterpret_cast<unsigned*>(&hv);
    }
    __syncthreads();

    int warp = tid >> 5;
    int lane = tid & 31;
    int tg = lane & 3, g = lane >> 2;
    int wrow = warp * 16;

    // ---- A fragments: 2 ksteps x 4 half2 regs ----
    unsigned a[2][4];
#pragma unroll
    for (int ks = 0; ks < 2; ks++) {
        a[ks][0] = smA2[wrow + g    ][ks * 8 + tg];
        a[ks][1] = smA2[wrow + g + 8][ks * 8 + tg];
        a[ks][2] = smA2[wrow + g    ][ks * 8 + tg + 4];
        a[ks][3] = smA2[wrow + g + 8][ks * 8 + tg + 4];
    }

    const uint4* bf = (const uint4*)g_Bfrag;

    // stmatrix target addresses (lanes 0-7: rows g tile, 8-15: rows g+8 tile)
    int rowSel  = lane & 7;
    int tileSel = (lane >> 3) & 1;
    unsigned stRowAddr = smem_u32(smC) + (unsigned)((wrow + tileSel * 8 + rowSel) * 144);

    // copy-out mapping: 4 iterations x (4 rows x 8 x 16B)
    int cr = lane >> 3;        // 0..3
    int cp = lane & 7;         // 16B piece

#pragma unroll 1
    for (int chunk = 0; chunk < 16; chunk++) {
#pragma unroll
        for (int ntc = 0; ntc < 8; ntc++) {
            int nt = chunk * 8 + ntc;
            uint4 q = bf[nt * 32 + lane];
            int col = nt * 8 + 2 * tg;
            float d0 = smBias[col], d1 = smBias[col + 1];
            float d2 = d0, d3 = d1;

#define MMA(av, b0v, b1v) \
            asm volatile("mma.sync.aligned.m16n8k16.row.col.f32.f16.f16.f32 " \
                "{%0,%1,%2,%3}, {%4,%5,%6,%7}, {%8,%9}, {%0,%1,%2,%3};" \
                : "+f"(d0), "+f"(d1), "+f"(d2), "+f"(d3) \
                : "r"(av[0]), "r"(av[1]), "r"(av[2]), "r"(av[3]), \
                  "r"(b0v), "r"(b1v));
            MMA(a[0], q.x, q.y)
            MMA(a[1], q.z, q.w)
#undef MMA

            __half2 h01 = __floats2half2_rn(d0, d1);
            __half2 h23 = __floats2half2_rn(d2, d3);
            asm volatile("stmatrix.sync.aligned.m8n8.x2.shared.b16 [%0], {%1,%2};"
                :: "r"(stRowAddr + (unsigned)(ntc * 16)),
                   "r"(*reinterpret_cast<unsigned*>(&h01)),
                   "r"(*reinterpret_cast<unsigned*>(&h23)) : "memory");
        }
        __syncwarp();
        // coalesced copy-out: this warp's 16 rows x 128B
#pragma unroll
        for (int i = 0; i < 4; i++) {
            int row = i * 4 + cr;   // 0..15
            uint4 v = *reinterpret_cast<const uint4*>(smC + (wrow + row) * 144 + cp * 16);
            *reinterpret_cast<uint4*>(
                reinterpret_cast<char*>(g_We + (size_t)(eBase + wrow + row) * HH + chunk * 64)
                + cp * 16) = v;
        }
        __syncwarp();
    }
}

// ---------------------------------------------------------------
// message + scatter:  agg[b,dst] += node[b,src] @ We[e]   (warp per edge)
// ---------------------------------------------------------------
__global__ __launch_bounds__(256) void k_msg(
    const int* __restrict__ esrc, const int* __restrict__ edst)
{
    int e    = (blockIdx.x * blockDim.x + threadIdx.x) >> 5;
    int lane = threadIdx.x & 31;
    if (e >= NE) return;

    int s = esrc[e];
    int d = edst[e];
    int hi = lane >> 4;
    int q  = lane & 15;

    float n0 = g_node[(size_t)s * H + lane];
    float n1 = g_node[(size_t)(NN + s) * H + lane];

    const __half2* w = (const __half2*)(g_We + (size_t)e * HH);
    float2 a0 = {0.f, 0.f}, a1 = {0.f, 0.f};
#pragma unroll
    for (int hb = 0; hb < H; hb += 2) {
        __half2 v = __ldcs(w + hb * 16 + lane);   // streaming, 128B/warp
        float2 wf = __half22float2(v);
        int hrow = hb + hi;
        float s0 = __shfl_sync(FULL, n0, hrow);
        float s1 = __shfl_sync(FULL, n1, hrow);
        a0.x = fmaf(s0, wf.x, a0.x); a0.y = fmaf(s0, wf.y, a0.y);
        a1.x = fmaf(s1, wf.x, a1.x); a1.y = fmaf(s1, wf.y, a1.y);
    }
    a0.x += __shfl_xor_sync(FULL, a0.x, 16);
    a0.y += __shfl_xor_sync(FULL, a0.y, 16);
    a1.x += __shfl_xor_sync(FULL, a1.x, 16);
    a1.y += __shfl_xor_sync(FULL, a1.y, 16);

    if (hi == 0) {
        float* p0 = g_agg + (size_t)d * H + 2 * q;
        float* p1 = g_agg + (size_t)(NN + d) * H + 2 * q;
        atomicAdd(p0,     a0.x);
        atomicAdd(p0 + 1, a0.y);
        atomicAdd(p1,     a1.x);
        atomicAdd(p1 + 1, a1.y);
    }
}

// ---------------------------------------------------------------
// node = relu(agg + conv_b); GRU update. Thread per (b,node).
// Re-zeros g_agg for the next step.
// ---------------------------------------------------------------
__global__ __launch_bounds__(256) void k_gru(
    const float* __restrict__ conv_b,
    const float* __restrict__ wih, const float* __restrict__ whh,
    const float* __restrict__ bih, const float* __restrict__ bhh,
    float* __restrict__ out, int write_out)
{
    int n = blockIdx.x * blockDim.x + threadIdx.x;
    if (n >= BB * NN) return;
    size_t base = (size_t)n * H;

    float nd[H], hd[H];
    {
        float4* av = (float4*)(g_agg + base);
        const float4* hv = (const float4*)(g_hidden + base);
        const float4* cv = (const float4*)conv_b;
        float4 z4 = {0.f, 0.f, 0.f, 0.f};
#pragma unroll
        for (int qq = 0; qq < 8; qq++) {
            float4 a = av[qq], c = cv[qq], h4 = hv[qq];
            av[qq] = z4;                       // re-zero agg for next step
            nd[4*qq+0] = fmaxf(a.x + c.x, 0.f);
            nd[4*qq+1] = fmaxf(a.y + c.y, 0.f);
            nd[4*qq+2] = fmaxf(a.z + c.z, 0.f);
            nd[4*qq+3] = fmaxf(a.w + c.w, 0.f);
            hd[4*qq+0] = h4.x; hd[4*qq+1] = h4.y; hd[4*qq+2] = h4.z; hd[4*qq+3] = h4.w;
        }
    }

    const float4* wi = (const float4*)wih;   // rows of 8 float4
    const float4* wh = (const float4*)whh;

#pragma unroll 1
    for (int o = 0; o < H; o++) {
        float xr = 0.f, xz = 0.f, xn = 0.f, hr = 0.f, hz = 0.f, hn = 0.f;
#pragma unroll
        for (int qq = 0; qq < 8; qq++) {
            float4 w;
#define DOT(accv, srcarr, row) { w = (row)[qq]; \
            accv = fmaf(srcarr[4*qq+0], w.x, accv); accv = fmaf(srcarr[4*qq+1], w.y, accv); \
            accv = fmaf(srcarr[4*qq+2], w.z, accv); accv = fmaf(srcarr[4*qq+3], w.w, accv); }
            DOT(xr, nd, wi + (size_t)(o)      * 8)
            DOT(xz, nd, wi + (size_t)(o + 32) * 8)
            DOT(xn, nd, wi + (size_t)(o + 64) * 8)
            DOT(hr, hd, wh + (size_t)(o)      * 8)
            DOT(hz, hd, wh + (size_t)(o + 32) * 8)
            DOT(hn, hd, wh + (size_t)(o + 64) * 8)
#undef DOT
        }
        float rg = fsigmoid(xr + hr + bih[o]      + bhh[o]);
        float zg = fsigmoid(xz + hz + bih[o + 32] + bhh[o + 32]);
        float ng = ftanh(xn + bih[o + 64] + rg * (hn + bhh[o + 64]));
        float hprev = hd[o];
        float newh = (1.f - zg) * ng + zg * hprev;
        g_hidden[base + o] = newh;
        g_node[base + o]   = newh;
        if (write_out) out[base + o] = newh;
    }
}

// ---------------------------------------------------------------
extern "C" void kernel_launch(void* const* d_in, const int* in_sizes, int n_in,
                              void* d_out, int out_size)
{
    const float* x      = (const float*)d_in[0];
    const float* rel    = (const float*)d_in[1];
    const float* pw1    = (const float*)d_in[2];
    const float* pb1    = (const float*)d_in[3];
    const float* pw2    = (const float*)d_in[4];
    const float* pb2    = (const float*)d_in[5];
    const float* ew1    = (const float*)d_in[6];
    const float* eb1    = (const float*)d_in[7];
    const float* ew2    = (const float*)d_in[8];
    const float* eb2    = (const float*)d_in[9];
    const float* conv_b = (const float*)d_in[10];
    const float* wih    = (const float*)d_in[11];
    const float* whh    = (const float*)d_in[12];
    const float* bih    = (const float*)d_in[13];
    const float* bhh    = (const float*)d_in[14];
    const int*   esrc   = (const int*)d_in[15];
    const int*   edst   = (const int*)d_in[16];
    float* out = (float*)d_out;

    k_h0<<<13824, 256>>>(x, pw1, pb1, pw2, pb2);
    k_prep<<<32, 256>>>(ew2);
    k_We_mma<<<3456, 128>>>(rel, ew1, eb1, eb2);   // 64 edges / block

    for (int s = 0; s < 3; s++) {
        k_msg<<<27648, 256>>>(esrc, edst);
        k_gru<<<432, 256>>>(conv_b, wih, whh, bih, bhh, out, (s == 2) ? 1 : 0);
    }
}